// round 4
// baseline (speedup 1.0000x reference)
#include <cuda_runtime.h>
#include <cuda_bf16.h>
#include <cstdint>

// Problem constants (ConvolutionLayer_17437567222234)
#define N_NODES 50000
#define N_EDGES 800000
#define D_IN    512
#define D_OUT   256
#define SCAN_THREADS 1024

// Scratch (device globals — no allocation allowed)
__device__ float g_h[(size_t)N_NODES * D_OUT];   // h = X @ W  (51.2 MB)
__device__ int   g_counts[N_NODES];
__device__ int   g_offsets[N_NODES + 1];
__device__ int   g_cursor[N_NODES];
__device__ int   g_esrc[N_EDGES];                // bucketed edge source index
__device__ float g_eval[N_EDGES];                // bucketed edge value
__device__ int   g_idx64;                        // 1 if edge indices are int64

// ---------------------------------------------------------------------------
// Index dtype detect (JAX x64 int64 vs default int32).
// int64-LE with values < 2^31 => odd 32-bit words of first 16 elems all zero.
// ---------------------------------------------------------------------------
__global__ void detect_idx_kernel(const int* __restrict__ src_as_i32)
{
    int is64 = 1;
    #pragma unroll
    for (int i = 1; i < 32; i += 2)
        if (src_as_i32[i] != 0) is64 = 0;
    g_idx64 = is64;
}

__device__ __forceinline__ int load_idx(const void* p, int e)
{
    if (g_idx64)
        return (int)__ldg(&reinterpret_cast<const long long*>(p)[e]);
    return __ldg(&reinterpret_cast<const int*>(p)[e]);
}

// ---------------------------------------------------------------------------
// TF32 helpers
// ---------------------------------------------------------------------------
__device__ __forceinline__ uint32_t f2tf32(float f)
{
    uint32_t u;
    asm("cvt.rna.tf32.f32 %0, %1;" : "=r"(u) : "f"(f));
    return u;
}

__device__ __forceinline__ void mma_tf32(float* c,
                                         uint32_t a0, uint32_t a1, uint32_t a2, uint32_t a3,
                                         uint32_t b0, uint32_t b1)
{
    asm volatile(
        "mma.sync.aligned.m16n8k8.row.col.f32.tf32.tf32.f32 "
        "{%0,%1,%2,%3}, {%4,%5,%6,%7}, {%8,%9}, {%0,%1,%2,%3};"
        : "+f"(c[0]), "+f"(c[1]), "+f"(c[2]), "+f"(c[3])
        : "r"(a0), "r"(a1), "r"(a2), "r"(a3), "r"(b0), "r"(b1));
}

// ---------------------------------------------------------------------------
// GEMM: C[M,N] = A[M,K] * B[K,N] via tf32 tensor-core MMA.
// BM=128, BN=128, BK=32. 256 threads = 8 warps (4 m x 2 n), warp tile 32x64.
// Register-prefetch double buffering: next tile's global loads issued before
// computing the current tile, hiding DRAM latency behind MMA work.
// ---------------------------------------------------------------------------
#define BK 32
#define SMP 136   // 128 + 8 pad words (conflict-free frag loads: 136%32==8)

__global__ __launch_bounds__(256, 1)
void gemm_tf32_kernel(const float* __restrict__ A,
                      const float* __restrict__ B,
                      float* __restrict__ C)
{
    const int M = N_NODES, N = D_OUT, K = D_IN;
    __shared__ uint32_t As[BK][SMP];   // [k][m], tf32 bits
    __shared__ uint32_t Bs[BK][SMP];   // [k][n], tf32 bits

    const int tid  = threadIdx.x;
    const int wid  = tid >> 5;
    const int lane = tid & 31;
    const int g    = lane >> 2;        // group id 0..7
    const int q    = lane & 3;         // thread-in-group 0..3

    const int row0 = blockIdx.y * 128;
    const int col0 = blockIdx.x * 128;
    const int m0   = (wid >> 1) * 32;  // warp m offset in tile
    const int n0   = (wid & 1) * 64;   // warp n offset in tile

    // staging maps
    const int a_row  = tid >> 1;             // 0..127
    const int a_kc   = (tid & 1) * 4;        // 0 or 4 (+8 per iter)
    const int b_krow = tid >> 3;             // 0..31
    const int b_nc4  = (tid & 7);            // float4 col (+8 per iter)

    const int  gr_a = row0 + a_row;
    const bool a_ok = (gr_a < M);

    float acc[2][8][4];
    #pragma unroll
    for (int mt = 0; mt < 2; mt++)
        #pragma unroll
        for (int nt = 0; nt < 8; nt++)
            #pragma unroll
            for (int r = 0; r < 4; r++) acc[mt][nt][r] = 0.0f;

    float4 a_pf[4], b_pf[4];

    // prime: load tile k0 = 0
    #pragma unroll
    for (int it = 0; it < 4; it++) {
        const int kc = a_kc + it * 8;
        a_pf[it] = a_ok ? *reinterpret_cast<const float4*>(&A[(size_t)gr_a * K + kc])
                        : make_float4(0.f, 0.f, 0.f, 0.f);
        const int nc4 = b_nc4 + it * 8;
        b_pf[it] = *reinterpret_cast<const float4*>(&B[(size_t)b_krow * N + col0 + nc4 * 4]);
    }

    for (int k0 = 0; k0 < K; k0 += BK) {
        // --- commit prefetched tile to smem (convert to tf32) ---
        #pragma unroll
        for (int it = 0; it < 4; it++) {
            const int kc = a_kc + it * 8;
            As[kc + 0][a_row] = f2tf32(a_pf[it].x);
            As[kc + 1][a_row] = f2tf32(a_pf[it].y);
            As[kc + 2][a_row] = f2tf32(a_pf[it].z);
            As[kc + 3][a_row] = f2tf32(a_pf[it].w);
            const int nc4 = b_nc4 + it * 8;
            Bs[b_krow][nc4 * 4 + 0] = f2tf32(b_pf[it].x);
            Bs[b_krow][nc4 * 4 + 1] = f2tf32(b_pf[it].y);
            Bs[b_krow][nc4 * 4 + 2] = f2tf32(b_pf[it].z);
            Bs[b_krow][nc4 * 4 + 3] = f2tf32(b_pf[it].w);
        }
        __syncthreads();

        // --- issue next tile's global loads (overlap with MMA below) ---
        const int kn = k0 + BK;
        if (kn < K) {
            #pragma unroll
            for (int it = 0; it < 4; it++) {
                const int kc = a_kc + it * 8;
                a_pf[it] = a_ok ? *reinterpret_cast<const float4*>(
                                      &A[(size_t)gr_a * K + kn + kc])
                                : make_float4(0.f, 0.f, 0.f, 0.f);
                const int nc4 = b_nc4 + it * 8;
                b_pf[it] = *reinterpret_cast<const float4*>(
                    &B[(size_t)(kn + b_krow) * N + col0 + nc4 * 4]);
            }
        }

        // --- compute: 4 k-steps of 8 ---
        #pragma unroll
        for (int ks = 0; ks < 4; ks++) {
            const int kb = ks * 8;
            uint32_t af[2][4];
            #pragma unroll
            for (int mt = 0; mt < 2; mt++) {
                const int r = m0 + mt * 16 + g;
                af[mt][0] = As[kb + q][r];
                af[mt][1] = As[kb + q][r + 8];
                af[mt][2] = As[kb + q + 4][r];
                af[mt][3] = As[kb + q + 4][r + 8];
            }
            uint32_t bf[8][2];
            #pragma unroll
            for (int nt = 0; nt < 8; nt++) {
                const int c = n0 + nt * 8 + g;
                bf[nt][0] = Bs[kb + q][c];
                bf[nt][1] = Bs[kb + q + 4][c];
            }
            #pragma unroll
            for (int mt = 0; mt < 2; mt++)
                #pragma unroll
                for (int nt = 0; nt < 8; nt++)
                    mma_tf32(acc[mt][nt],
                             af[mt][0], af[mt][1], af[mt][2], af[mt][3],
                             bf[nt][0], bf[nt][1]);
        }
        __syncthreads();
    }

    // --- epilogue: c0,c1 -> (row, 2q),(row,2q+1); c2,c3 -> row+8 ---
    #pragma unroll
    for (int mt = 0; mt < 2; mt++) {
        const int r_lo = row0 + m0 + mt * 16 + g;
        const int r_hi = r_lo + 8;
        #pragma unroll
        for (int nt = 0; nt < 8; nt++) {
            const int c = col0 + n0 + nt * 8 + 2 * q;
            if (r_lo < M)
                *reinterpret_cast<float2*>(&C[(size_t)r_lo * N + c]) =
                    make_float2(acc[mt][nt][0], acc[mt][nt][1]);
            if (r_hi < M)
                *reinterpret_cast<float2*>(&C[(size_t)r_hi * N + c]) =
                    make_float2(acc[mt][nt][2], acc[mt][nt][3]);
        }
    }
}

// ---------------------------------------------------------------------------
// CSR build
// ---------------------------------------------------------------------------
__global__ void zero_counts_kernel()
{
    int i = blockIdx.x * blockDim.x + threadIdx.x;
    if (i < N_NODES) g_counts[i] = 0;
}

__global__ void count_kernel(const void* __restrict__ dstp)
{
    int e = blockIdx.x * blockDim.x + threadIdx.x;
    if (e >= N_EDGES) return;
    atomicAdd(&g_counts[load_idx(dstp, e)], 1);
}

// Single-block scan over 50K counts -> exclusive offsets (+ cursor copy).
__global__ __launch_bounds__(SCAN_THREADS)
void scan_kernel()
{
    __shared__ int part[SCAN_THREADS];
    const int t  = threadIdx.x;
    const int CH = (N_NODES + SCAN_THREADS - 1) / SCAN_THREADS;  // 49
    const int base = t * CH;

    int s = 0;
    for (int i = 0; i < CH; i++) {
        int idx = base + i;
        if (idx < N_NODES) s += g_counts[idx];
    }
    part[t] = s;
    __syncthreads();

    for (int off = 1; off < SCAN_THREADS; off <<= 1) {
        int v = (t >= off) ? part[t - off] : 0;
        __syncthreads();
        part[t] += v;
        __syncthreads();
    }

    int run = (t == 0) ? 0 : part[t - 1];
    for (int i = 0; i < CH; i++) {
        int idx = base + i;
        if (idx < N_NODES) {
            g_offsets[idx] = run;
            g_cursor[idx]  = run;
            run += g_counts[idx];
        }
    }
    if (t == SCAN_THREADS - 1) g_offsets[N_NODES] = run;
}

__global__ void fill_kernel(const void* __restrict__ srcp,
                            const void* __restrict__ dstp,
                            const float* __restrict__ vals)
{
    int e = blockIdx.x * blockDim.x + threadIdx.x;
    if (e >= N_EDGES) return;
    int d   = load_idx(dstp, e);
    int pos = atomicAdd(&g_cursor[d], 1);
    g_esrc[pos] = load_idx(srcp, e);
    g_eval[pos] = __ldg(&vals[e]);
}

// ---------------------------------------------------------------------------
// Gather-aggregate + ReLU.  One warp per destination node; each lane owns
// 8 output columns (2 float4).  h rows are L2-resident (51.2 MB < 126 MB).
// ---------------------------------------------------------------------------
__global__ __launch_bounds__(256)
void gather_kernel(const float* __restrict__ h, float* __restrict__ out)
{
    const int node = blockIdx.x * 8 + (threadIdx.x >> 5);
    const int lane = threadIdx.x & 31;
    if (node >= N_NODES) return;

    const int beg = g_offsets[node];
    const int end = g_offsets[node + 1];

    float4 acc0 = make_float4(0.f, 0.f, 0.f, 0.f);
    float4 acc1 = make_float4(0.f, 0.f, 0.f, 0.f);

    int j = beg;
    for (; j + 1 < end; j += 2) {
        const int   s0 = __ldg(&g_esrc[j]);
        const float v0 = __ldg(&g_eval[j]);
        const int   s1 = __ldg(&g_esrc[j + 1]);
        const float v1 = __ldg(&g_eval[j + 1]);
        const float4* r0 = reinterpret_cast<const float4*>(h + (size_t)s0 * D_OUT);
        const float4* r1 = reinterpret_cast<const float4*>(h + (size_t)s1 * D_OUT);
        float4 a0 = __ldg(&r0[lane]);
        float4 b0 = __ldg(&r0[lane + 32]);
        float4 a1 = __ldg(&r1[lane]);
        float4 b1 = __ldg(&r1[lane + 32]);
        acc0.x += a0.x * v0; acc0.y += a0.y * v0; acc0.z += a0.z * v0; acc0.w += a0.w * v0;
        acc1.x += b0.x * v0; acc1.y += b0.y * v0; acc1.z += b0.z * v0; acc1.w += b0.w * v0;
        acc0.x += a1.x * v1; acc0.y += a1.y * v1; acc0.z += a1.z * v1; acc0.w += a1.w * v1;
        acc1.x += b1.x * v1; acc1.y += b1.y * v1; acc1.z += b1.z * v1; acc1.w += b1.w * v1;
    }
    if (j < end) {
        const int   s0 = __ldg(&g_esrc[j]);
        const float v0 = __ldg(&g_eval[j]);
        const float4* r0 = reinterpret_cast<const float4*>(h + (size_t)s0 * D_OUT);
        float4 a0 = __ldg(&r0[lane]);
        float4 b0 = __ldg(&r0[lane + 32]);
        acc0.x += a0.x * v0; acc0.y += a0.y * v0; acc0.z += a0.z * v0; acc0.w += a0.w * v0;
        acc1.x += b0.x * v0; acc1.y += b0.y * v0; acc1.z += b0.z * v0; acc1.w += b0.w * v0;
    }

    acc0.x = fmaxf(acc0.x, 0.f); acc0.y = fmaxf(acc0.y, 0.f);
    acc0.z = fmaxf(acc0.z, 0.f); acc0.w = fmaxf(acc0.w, 0.f);
    acc1.x = fmaxf(acc1.x, 0.f); acc1.y = fmaxf(acc1.y, 0.f);
    acc1.z = fmaxf(acc1.z, 0.f); acc1.w = fmaxf(acc1.w, 0.f);

    float4* orow = reinterpret_cast<float4*>(out + (size_t)node * D_OUT);
    orow[lane]      = acc0;
    orow[lane + 32] = acc1;
}

// ---------------------------------------------------------------------------
// Launch.  Inputs (metadata order): x [N,512] f32, W [512,256] f32,
// edge_vals [E] f32, edge_src [E] int, edge_dst [E] int.  Output [N,256] f32.
// ---------------------------------------------------------------------------
extern "C" void kernel_launch(void* const* d_in, const int* in_sizes, int n_in,
                              void* d_out, int out_size)
{
    const float* x    = (const float*)d_in[0];
    const float* W    = (const float*)d_in[1];
    const float* vals = (const float*)d_in[2];
    const void*  src  = d_in[3];
    const void*  dst  = d_in[4];
    float* out = (float*)d_out;

    float* h;
    cudaGetSymbolAddress((void**)&h, g_h);

    // 1) GEMM: h = x @ W  (tf32 tensor cores, register-prefetch pipeline)
    dim3 gemm_grid(D_OUT / 128, (N_NODES + 127) / 128);
    gemm_tf32_kernel<<<gemm_grid, 256>>>(x, W, h);

    // 2) index dtype detect (before count/fill which use it)
    detect_idx_kernel<<<1, 1>>>((const int*)src);

    // 3) CSR build
    zero_counts_kernel<<<(N_NODES + 255) / 256, 256>>>();
    count_kernel<<<(N_EDGES + 255) / 256, 256>>>(dst);
    scan_kernel<<<1, SCAN_THREADS>>>();
    fill_kernel<<<(N_EDGES + 255) / 256, 256>>>(src, dst, vals);

    // 4) gather-aggregate + ReLU (one warp per node)
    gather_kernel<<<(N_NODES + 7) / 8, 256>>>(h, out);
}

// round 7
// speedup vs baseline: 1.0716x; 1.0716x over previous
#include <cuda_runtime.h>
#include <cuda_bf16.h>
#include <cstdint>

// Problem constants (ConvolutionLayer_17437567222234)
#define N_NODES 50000
#define N_EDGES 800000
#define D_IN    512
#define D_OUT   256
#define SCAN_THREADS 1024

// Scratch (device globals — no allocation allowed)
__device__ float g_h[(size_t)N_NODES * D_OUT];   // h = X @ W  (51.2 MB)
__device__ int   g_counts[N_NODES];
__device__ int   g_offsets[N_NODES + 1];
__device__ int   g_cursor[N_NODES];
__device__ int   g_esrc[N_EDGES];                // bucketed edge source index
__device__ float g_eval[N_EDGES];                // bucketed edge value
__device__ int   g_idx64;                        // 1 if edge indices are int64

// ---------------------------------------------------------------------------
// Fused: zero counts + detect int64/int32 edge-index dtype.
// int64-LE with values < 2^31 => odd 32-bit words of first 16 elems all zero.
// ---------------------------------------------------------------------------
__global__ void zero_detect_kernel(const int* __restrict__ src_as_i32)
{
    int i = blockIdx.x * blockDim.x + threadIdx.x;
    if (i < N_NODES) g_counts[i] = 0;
    if (i == 0) {
        int is64 = 1;
        #pragma unroll
        for (int k = 1; k < 32; k += 2)
            if (src_as_i32[k] != 0) is64 = 0;
        g_idx64 = is64;
    }
}

__device__ __forceinline__ int load_idx(const void* p, int e)
{
    if (g_idx64)
        return (int)__ldg(&reinterpret_cast<const long long*>(p)[e]);
    return __ldg(&reinterpret_cast<const int*>(p)[e]);
}

// ---------------------------------------------------------------------------
// TF32 helpers
// ---------------------------------------------------------------------------
__device__ __forceinline__ uint32_t f2tf32(float f)
{
    uint32_t u;
    asm("cvt.rna.tf32.f32 %0, %1;" : "=r"(u) : "f"(f));
    return u;
}

__device__ __forceinline__ void mma_tf32(float* c,
                                         uint32_t a0, uint32_t a1, uint32_t a2, uint32_t a3,
                                         uint32_t b0, uint32_t b1)
{
    asm volatile(
        "mma.sync.aligned.m16n8k8.row.col.f32.tf32.tf32.f32 "
        "{%0,%1,%2,%3}, {%4,%5,%6,%7}, {%8,%9}, {%0,%1,%2,%3};"
        : "+f"(c[0]), "+f"(c[1]), "+f"(c[2]), "+f"(c[3])
        : "r"(a0), "r"(a1), "r"(a2), "r"(a3), "r"(b0), "r"(b1));
}

// ---------------------------------------------------------------------------
// GEMM: C[M,N] = A[M,K] * B[K,N] via tf32 tensor-core MMA.
// BM=128, BN=128, BK=32. 256 threads = 8 warps (4 m x 2 n), warp tile 32x64.
// Register-prefetch double buffering; prefetch loads batched for high MLP.
// ---------------------------------------------------------------------------
#define BK 32
#define SMP 136   // 128 + 8 pad words (conflict-free frag loads: 136%32==8)

__global__ __launch_bounds__(256, 1)
void gemm_tf32_kernel(const float* __restrict__ A,
                      const float* __restrict__ B,
                      float* __restrict__ C)
{
    const int M = N_NODES, N = D_OUT, K = D_IN;
    __shared__ uint32_t As[BK][SMP];   // [k][m], tf32 bits
    __shared__ uint32_t Bs[BK][SMP];   // [k][n], tf32 bits

    const int tid  = threadIdx.x;
    const int wid  = tid >> 5;
    const int lane = tid & 31;
    const int g    = lane >> 2;
    const int q    = lane & 3;

    const int row0 = blockIdx.y * 128;
    const int col0 = blockIdx.x * 128;
    const int m0   = (wid >> 1) * 32;
    const int n0   = (wid & 1) * 64;

    const int a_row  = tid >> 1;
    const int a_kc   = (tid & 1) * 4;
    const int b_krow = tid >> 3;
    const int b_nc4  = (tid & 7);

    const int  gr_a = row0 + a_row;
    const bool a_ok = (gr_a < M);

    float acc[2][8][4];
    #pragma unroll
    for (int mt = 0; mt < 2; mt++)
        #pragma unroll
        for (int nt = 0; nt < 8; nt++)
            #pragma unroll
            for (int r = 0; r < 4; r++) acc[mt][nt][r] = 0.0f;

    float4 a_pf[4], b_pf[4];

    // prime tile 0: batch all A loads, then all B loads (max MLP)
    #pragma unroll
    for (int it = 0; it < 4; it++) {
        const int kc = a_kc + it * 8;
        a_pf[it] = a_ok ? *reinterpret_cast<const float4*>(&A[(size_t)gr_a * K + kc])
                        : make_float4(0.f, 0.f, 0.f, 0.f);
    }
    #pragma unroll
    for (int it = 0; it < 4; it++) {
        const int nc4 = b_nc4 + it * 8;
        b_pf[it] = *reinterpret_cast<const float4*>(&B[(size_t)b_krow * N + col0 + nc4 * 4]);
    }

    for (int k0 = 0; k0 < K; k0 += BK) {
        // commit prefetched tile to smem (convert to tf32)
        #pragma unroll
        for (int it = 0; it < 4; it++) {
            const int kc = a_kc + it * 8;
            As[kc + 0][a_row] = f2tf32(a_pf[it].x);
            As[kc + 1][a_row] = f2tf32(a_pf[it].y);
            As[kc + 2][a_row] = f2tf32(a_pf[it].z);
            As[kc + 3][a_row] = f2tf32(a_pf[it].w);
            const int nc4 = b_nc4 + it * 8;
            Bs[b_krow][nc4 * 4 + 0] = f2tf32(b_pf[it].x);
            Bs[b_krow][nc4 * 4 + 1] = f2tf32(b_pf[it].y);
            Bs[b_krow][nc4 * 4 + 2] = f2tf32(b_pf[it].z);
            Bs[b_krow][nc4 * 4 + 3] = f2tf32(b_pf[it].w);
        }
        __syncthreads();

        // issue next tile's global loads in one batch (overlap with MMAs)
        const int kn = k0 + BK;
        if (kn < K) {
            #pragma unroll
            for (int it = 0; it < 4; it++) {
                const int kc = a_kc + it * 8;
                a_pf[it] = a_ok ? *reinterpret_cast<const float4*>(
                                      &A[(size_t)gr_a * K + kn + kc])
                                : make_float4(0.f, 0.f, 0.f, 0.f);
            }
            #pragma unroll
            for (int it = 0; it < 4; it++) {
                const int nc4 = b_nc4 + it * 8;
                b_pf[it] = *reinterpret_cast<const float4*>(
                    &B[(size_t)(kn + b_krow) * N + col0 + nc4 * 4]);
            }
        }

        // compute: 4 k-steps of 8
        #pragma unroll
        for (int ks = 0; ks < 4; ks++) {
            const int kb = ks * 8;
            uint32_t af[2][4];
            #pragma unroll
            for (int mt = 0; mt < 2; mt++) {
                const int r = m0 + mt * 16 + g;
                af[mt][0] = As[kb + q][r];
                af[mt][1] = As[kb + q][r + 8];
                af[mt][2] = As[kb + q + 4][r];
                af[mt][3] = As[kb + q + 4][r + 8];
            }
            uint32_t bf[8][2];
            #pragma unroll
            for (int nt = 0; nt < 8; nt++) {
                const int c = n0 + nt * 8 + g;
                bf[nt][0] = Bs[kb + q][c];
                bf[nt][1] = Bs[kb + q + 4][c];
            }
            #pragma unroll
            for (int mt = 0; mt < 2; mt++)
                #pragma unroll
                for (int nt = 0; nt < 8; nt++)
                    mma_tf32(acc[mt][nt],
                             af[mt][0], af[mt][1], af[mt][2], af[mt][3],
                             bf[nt][0], bf[nt][1]);
        }
        __syncthreads();
    }

    #pragma unroll
    for (int mt = 0; mt < 2; mt++) {
        const int r_lo = row0 + m0 + mt * 16 + g;
        const int r_hi = r_lo + 8;
        #pragma unroll
        for (int nt = 0; nt < 8; nt++) {
            const int c = col0 + n0 + nt * 8 + 2 * q;
            if (r_lo < M)
                *reinterpret_cast<float2*>(&C[(size_t)r_lo * N + c]) =
                    make_float2(acc[mt][nt][0], acc[mt][nt][1]);
            if (r_hi < M)
                *reinterpret_cast<float2*>(&C[(size_t)r_hi * N + c]) =
                    make_float2(acc[mt][nt][2], acc[mt][nt][3]);
        }
    }
}

// ---------------------------------------------------------------------------
// CSR build
// ---------------------------------------------------------------------------
__global__ void count_kernel(const void* __restrict__ dstp)
{
    int e = blockIdx.x * blockDim.x + threadIdx.x;
    if (e >= N_EDGES) return;
    atomicAdd(&g_counts[load_idx(dstp, e)], 1);
}

__global__ __launch_bounds__(SCAN_THREADS)
void scan_kernel()
{
    __shared__ int part[SCAN_THREADS];
    const int t  = threadIdx.x;
    const int CH = (N_NODES + SCAN_THREADS - 1) / SCAN_THREADS;  // 49
    const int base = t * CH;

    int s = 0;
    for (int i = 0; i < CH; i++) {
        int idx = base + i;
        if (idx < N_NODES) s += g_counts[idx];
    }
    part[t] = s;
    __syncthreads();

    for (int off = 1; off < SCAN_THREADS; off <<= 1) {
        int v = (t >= off) ? part[t - off] : 0;
        __syncthreads();
        part[t] += v;
        __syncthreads();
    }

    int run = (t == 0) ? 0 : part[t - 1];
    for (int i = 0; i < CH; i++) {
        int idx = base + i;
        if (idx < N_NODES) {
            g_offsets[idx] = run;
            g_cursor[idx]  = run;
            run += g_counts[idx];
        }
    }
    if (t == SCAN_THREADS - 1) g_offsets[N_NODES] = run;
}

__global__ void fill_kernel(const void* __restrict__ srcp,
                            const void* __restrict__ dstp,
                            const float* __restrict__ vals)
{
    int e = blockIdx.x * blockDim.x + threadIdx.x;
    if (e >= N_EDGES) return;
    int d   = load_idx(dstp, e);
    int pos = atomicAdd(&g_cursor[d], 1);
    g_esrc[pos] = load_idx(srcp, e);
    g_eval[pos] = __ldg(&vals[e]);
}

// ---------------------------------------------------------------------------
// Gather-aggregate + ReLU.  One warp per destination node; each lane owns
// 8 output columns (2 float4).  Unroll 4 edges -> 8 LDG.128 in flight/lane.
// ---------------------------------------------------------------------------
__global__ __launch_bounds__(256)
void gather_kernel(const float* __restrict__ h, float* __restrict__ out)
{
    const int node = blockIdx.x * 8 + (threadIdx.x >> 5);
    const int lane = threadIdx.x & 31;
    if (node >= N_NODES) return;

    const int beg = g_offsets[node];
    const int end = g_offsets[node + 1];

    float4 acc0 = make_float4(0.f, 0.f, 0.f, 0.f);
    float4 acc1 = make_float4(0.f, 0.f, 0.f, 0.f);

    int j = beg;
    for (; j + 3 < end; j += 4) {
        int   s[4];
        float v[4];
        #pragma unroll
        for (int u = 0; u < 4; u++) {
            s[u] = __ldg(&g_esrc[j + u]);
            v[u] = __ldg(&g_eval[j + u]);
        }
        float4 a[4], b[4];
        #pragma unroll
        for (int u = 0; u < 4; u++) {
            const float4* r = reinterpret_cast<const float4*>(h + (size_t)s[u] * D_OUT);
            a[u] = __ldg(&r[lane]);
            b[u] = __ldg(&r[lane + 32]);
        }
        #pragma unroll
        for (int u = 0; u < 4; u++) {
            acc0.x += a[u].x * v[u]; acc0.y += a[u].y * v[u];
            acc0.z += a[u].z * v[u]; acc0.w += a[u].w * v[u];
            acc1.x += b[u].x * v[u]; acc1.y += b[u].y * v[u];
            acc1.z += b[u].z * v[u]; acc1.w += b[u].w * v[u];
        }
    }
    for (; j < end; j++) {
        const int   s0 = __ldg(&g_esrc[j]);
        const float v0 = __ldg(&g_eval[j]);
        const float4* r0 = reinterpret_cast<const float4*>(h + (size_t)s0 * D_OUT);
        float4 a0 = __ldg(&r0[lane]);
        float4 b0 = __ldg(&r0[lane + 32]);
        acc0.x += a0.x * v0; acc0.y += a0.y * v0; acc0.z += a0.z * v0; acc0.w += a0.w * v0;
        acc1.x += b0.x * v0; acc1.y += b0.y * v0; acc1.z += b0.z * v0; acc1.w += b0.w * v0;
    }

    acc0.x = fmaxf(acc0.x, 0.f); acc0.y = fmaxf(acc0.y, 0.f);
    acc0.z = fmaxf(acc0.z, 0.f); acc0.w = fmaxf(acc0.w, 0.f);
    acc1.x = fmaxf(acc1.x, 0.f); acc1.y = fmaxf(acc1.y, 0.f);
    acc1.z = fmaxf(acc1.z, 0.f); acc1.w = fmaxf(acc1.w, 0.f);

    float4* orow = reinterpret_cast<float4*>(out + (size_t)node * D_OUT);
    orow[lane]      = acc0;
    orow[lane + 32] = acc1;
}

// ---------------------------------------------------------------------------
// Launch.  CSR build runs on a side stream concurrently with the GEMM;
// gather joins both.  Stream/events created once on the first (non-captured)
// correctness call; identical work is enqueued on every call.
// ---------------------------------------------------------------------------
extern "C" void kernel_launch(void* const* d_in, const int* in_sizes, int n_in,
                              void* d_out, int out_size)
{
    const float* x    = (const float*)d_in[0];
    const float* W    = (const float*)d_in[1];
    const float* vals = (const float*)d_in[2];
    const void*  src  = d_in[3];
    const void*  dst  = d_in[4];
    float* out = (float*)d_out;

    float* h;
    cudaGetSymbolAddress((void**)&h, g_h);

    static cudaStream_t side = nullptr;
    static cudaEvent_t  e_fork = nullptr, e_join = nullptr;
    if (side == nullptr) {
        cudaStreamCreateWithFlags(&side, cudaStreamNonBlocking);
        cudaEventCreateWithFlags(&e_fork, cudaEventDisableTiming);
        cudaEventCreateWithFlags(&e_join, cudaEventDisableTiming);
    }

    // fork: side stream joins the capture after this point
    cudaEventRecord(e_fork, 0);
    cudaStreamWaitEvent(side, e_fork, 0);

    // --- side stream: CSR build (independent of GEMM) ---
    zero_detect_kernel<<<(N_NODES + 255) / 256, 256, 0, side>>>((const int*)src);
    count_kernel<<<(N_EDGES + 255) / 256, 256, 0, side>>>(dst);
    scan_kernel<<<1, SCAN_THREADS, 0, side>>>();
    fill_kernel<<<(N_EDGES + 255) / 256, 256, 0, side>>>(src, dst, vals);
    cudaEventRecord(e_join, side);

    // --- main stream: GEMM h = x @ W (overlapped with CSR build) ---
    dim3 gemm_grid(D_OUT / 128, (N_NODES + 127) / 128);
    gemm_tf32_kernel<<<gemm_grid, 256>>>(x, W, h);

    // join, then gather-aggregate + ReLU
    cudaStreamWaitEvent(0, e_join, 0);
    gather_kernel<<<(N_NODES + 7) / 8, 256>>>(h, out);
}

// round 14
// speedup vs baseline: 1.1523x; 1.0753x over previous
#include <cuda_runtime.h>
#include <cuda_fp16.h>
#include <cstdint>

// Problem constants (ConvolutionLayer_17437567222234)
#define N_NODES 50000
#define N_EDGES 800000
#define D_IN    512
#define D_OUT   256
#define SCAN_THREADS 1024

// Scratch (device globals — no allocation allowed)
__device__ __half g_h[(size_t)N_NODES * D_OUT];  // h = X @ W (fp16, 25.6 MB)
__device__ int   g_counts[N_NODES];
__device__ int   g_offsets[N_NODES + 1];
__device__ int   g_cursor[N_NODES];
__device__ int   g_esrc[N_EDGES];                // bucketed edge source index
__device__ float g_eval[N_EDGES];                // bucketed edge value
__device__ int   g_idx64;                        // 1 if edge indices are int64

// ---------------------------------------------------------------------------
// Fused: zero counts + detect int64/int32 edge-index dtype.
// ---------------------------------------------------------------------------
__global__ void zero_detect_kernel(const int* __restrict__ src_as_i32)
{
    int i = blockIdx.x * blockDim.x + threadIdx.x;
    if (i < N_NODES) g_counts[i] = 0;
    if (i == 0) {
        int is64 = 1;
        #pragma unroll
        for (int k = 1; k < 32; k += 2)
            if (src_as_i32[k] != 0) is64 = 0;
        g_idx64 = is64;
    }
}

__device__ __forceinline__ int load_idx(const void* p, int e)
{
    if (g_idx64)
        return (int)__ldg(&reinterpret_cast<const long long*>(p)[e]);
    return __ldg(&reinterpret_cast<const int*>(p)[e]);
}

// ---------------------------------------------------------------------------
// TF32 helpers
// ---------------------------------------------------------------------------
__device__ __forceinline__ uint32_t f2tf32(float f)
{
    uint32_t u;
    asm("cvt.rna.tf32.f32 %0, %1;" : "=r"(u) : "f"(f));
    return u;
}

__device__ __forceinline__ void mma_tf32(float* c,
                                         uint32_t a0, uint32_t a1, uint32_t a2, uint32_t a3,
                                         uint32_t b0, uint32_t b1)
{
    asm volatile(
        "mma.sync.aligned.m16n8k8.row.col.f32.tf32.tf32.f32 "
        "{%0,%1,%2,%3}, {%4,%5,%6,%7}, {%8,%9}, {%0,%1,%2,%3};"
        : "+f"(c[0]), "+f"(c[1]), "+f"(c[2]), "+f"(c[3])
        : "r"(a0), "r"(a1), "r"(a2), "r"(a3), "r"(b0), "r"(b1));
}

// ---------------------------------------------------------------------------
// GEMM: C[M,N] = A[M,K] * B[K,N] via tf32 tensor-core MMA; fp16 output.
// BM=128, BN=128, BK=32. 256 threads = 8 warps (4 m x 2 n), warp tile 32x64.
// Register-prefetch double buffering; prefetch loads batched for high MLP.
// ---------------------------------------------------------------------------
#define BK 32
#define SMP 136   // 128 + 8 pad words (conflict-free frag loads: 136%32==8)

__global__ __launch_bounds__(256, 1)
void gemm_tf32_kernel(const float* __restrict__ A,
                      const float* __restrict__ B,
                      __half* __restrict__ C)
{
    const int M = N_NODES, N = D_OUT, K = D_IN;
    __shared__ uint32_t As[BK][SMP];   // [k][m], tf32 bits
    __shared__ uint32_t Bs[BK][SMP];   // [k][n], tf32 bits

    const int tid  = threadIdx.x;
    const int wid  = tid >> 5;
    const int lane = tid & 31;
    const int g    = lane >> 2;
    const int q    = lane & 3;

    const int row0 = blockIdx.y * 128;
    const int col0 = blockIdx.x * 128;
    const int m0   = (wid >> 1) * 32;
    const int n0   = (wid & 1) * 64;

    const int a_row  = tid >> 1;
    const int a_kc   = (tid & 1) * 4;
    const int b_krow = tid >> 3;
    const int b_nc4  = (tid & 7);

    const int  gr_a = row0 + a_row;
    const bool a_ok = (gr_a < M);

    float acc[2][8][4];
    #pragma unroll
    for (int mt = 0; mt < 2; mt++)
        #pragma unroll
        for (int nt = 0; nt < 8; nt++)
            #pragma unroll
            for (int r = 0; r < 4; r++) acc[mt][nt][r] = 0.0f;

    float4 a_pf[4], b_pf[4];

    // prime tile 0 (batched loads for max MLP)
    #pragma unroll
    for (int it = 0; it < 4; it++) {
        const int kc = a_kc + it * 8;
        a_pf[it] = a_ok ? *reinterpret_cast<const float4*>(&A[(size_t)gr_a * K + kc])
                        : make_float4(0.f, 0.f, 0.f, 0.f);
    }
    #pragma unroll
    for (int it = 0; it < 4; it++) {
        const int nc4 = b_nc4 + it * 8;
        b_pf[it] = *reinterpret_cast<const float4*>(&B[(size_t)b_krow * N + col0 + nc4 * 4]);
    }

    for (int k0 = 0; k0 < K; k0 += BK) {
        #pragma unroll
        for (int it = 0; it < 4; it++) {
            const int kc = a_kc + it * 8;
            As[kc + 0][a_row] = f2tf32(a_pf[it].x);
            As[kc + 1][a_row] = f2tf32(a_pf[it].y);
            As[kc + 2][a_row] = f2tf32(a_pf[it].z);
            As[kc + 3][a_row] = f2tf32(a_pf[it].w);
            const int nc4 = b_nc4 + it * 8;
            Bs[b_krow][nc4 * 4 + 0] = f2tf32(b_pf[it].x);
            Bs[b_krow][nc4 * 4 + 1] = f2tf32(b_pf[it].y);
            Bs[b_krow][nc4 * 4 + 2] = f2tf32(b_pf[it].z);
            Bs[b_krow][nc4 * 4 + 3] = f2tf32(b_pf[it].w);
        }
        __syncthreads();

        const int kn = k0 + BK;
        if (kn < K) {
            #pragma unroll
            for (int it = 0; it < 4; it++) {
                const int kc = a_kc + it * 8;
                a_pf[it] = a_ok ? *reinterpret_cast<const float4*>(
                                      &A[(size_t)gr_a * K + kn + kc])
                                : make_float4(0.f, 0.f, 0.f, 0.f);
            }
            #pragma unroll
            for (int it = 0; it < 4; it++) {
                const int nc4 = b_nc4 + it * 8;
                b_pf[it] = *reinterpret_cast<const float4*>(
                    &B[(size_t)(kn + b_krow) * N + col0 + nc4 * 4]);
            }
        }

        #pragma unroll
        for (int ks = 0; ks < 4; ks++) {
            const int kb = ks * 8;
            uint32_t af[2][4];
            #pragma unroll
            for (int mt = 0; mt < 2; mt++) {
                const int r = m0 + mt * 16 + g;
                af[mt][0] = As[kb + q][r];
                af[mt][1] = As[kb + q][r + 8];
                af[mt][2] = As[kb + q + 4][r];
                af[mt][3] = As[kb + q + 4][r + 8];
            }
            uint32_t bf[8][2];
            #pragma unroll
            for (int nt = 0; nt < 8; nt++) {
                const int c = n0 + nt * 8 + g;
                bf[nt][0] = Bs[kb + q][c];
                bf[nt][1] = Bs[kb + q + 4][c];
            }
            #pragma unroll
            for (int mt = 0; mt < 2; mt++)
                #pragma unroll
                for (int nt = 0; nt < 8; nt++)
                    mma_tf32(acc[mt][nt],
                             af[mt][0], af[mt][1], af[mt][2], af[mt][3],
                             bf[nt][0], bf[nt][1]);
        }
        __syncthreads();
    }

    // epilogue: fp16 output; c0,c1 -> (row, 2q),(row,2q+1); c2,c3 -> row+8
    #pragma unroll
    for (int mt = 0; mt < 2; mt++) {
        const int r_lo = row0 + m0 + mt * 16 + g;
        const int r_hi = r_lo + 8;
        #pragma unroll
        for (int nt = 0; nt < 8; nt++) {
            const int c = col0 + n0 + nt * 8 + 2 * q;
            if (r_lo < M) {
                __half2 p = __floats2half2_rn(acc[mt][nt][0], acc[mt][nt][1]);
                *reinterpret_cast<__half2*>(&C[(size_t)r_lo * N + c]) = p;
            }
            if (r_hi < M) {
                __half2 p = __floats2half2_rn(acc[mt][nt][2], acc[mt][nt][3]);
                *reinterpret_cast<__half2*>(&C[(size_t)r_hi * N + c]) = p;
            }
        }
    }
}

// ---------------------------------------------------------------------------
// CSR build
// ---------------------------------------------------------------------------
__global__ void count_kernel(const void* __restrict__ dstp)
{
    int e = blockIdx.x * blockDim.x + threadIdx.x;
    if (e >= N_EDGES) return;
    atomicAdd(&g_counts[load_idx(dstp, e)], 1);
}

__global__ __launch_bounds__(SCAN_THREADS)
void scan_kernel()
{
    __shared__ int part[SCAN_THREADS];
    const int t  = threadIdx.x;
    const int CH = (N_NODES + SCAN_THREADS - 1) / SCAN_THREADS;  // 49
    const int base = t * CH;

    int s = 0;
    for (int i = 0; i < CH; i++) {
        int idx = base + i;
        if (idx < N_NODES) s += g_counts[idx];
    }
    part[t] = s;
    __syncthreads();

    for (int off = 1; off < SCAN_THREADS; off <<= 1) {
        int v = (t >= off) ? part[t - off] : 0;
        __syncthreads();
        part[t] += v;
        __syncthreads();
    }

    int run = (t == 0) ? 0 : part[t - 1];
    for (int i = 0; i < CH; i++) {
        int idx = base + i;
        if (idx < N_NODES) {
            g_offsets[idx] = run;
            g_cursor[idx]  = run;
            run += g_counts[idx];
        }
    }
    if (t == SCAN_THREADS - 1) g_offsets[N_NODES] = run;
}

__global__ void fill_kernel(const void* __restrict__ srcp,
                            const void* __restrict__ dstp,
                            const float* __restrict__ vals)
{
    int e = blockIdx.x * blockDim.x + threadIdx.x;
    if (e >= N_EDGES) return;
    int d   = load_idx(dstp, e);
    int pos = atomicAdd(&g_cursor[d], 1);
    g_esrc[pos] = load_idx(srcp, e);
    g_eval[pos] = __ldg(&vals[e]);
}

// ---------------------------------------------------------------------------
// Gather-aggregate + ReLU.  One warp per destination node; each lane owns
// 8 consecutive output columns = 1 uint4 (8 fp16) load per edge.
// Unroll 4 edges -> 4 LDG.128 in flight per lane.  fp32 accumulation.
// ---------------------------------------------------------------------------
__global__ __launch_bounds__(256)
void gather_kernel(const __half* __restrict__ h, float* __restrict__ out)
{
    const int node = blockIdx.x * 8 + (threadIdx.x >> 5);
    const int lane = threadIdx.x & 31;
    if (node >= N_NODES) return;

    const int beg = g_offsets[node];
    const int end = g_offsets[node + 1];

    float acc[8];
    #pragma unroll
    for (int i = 0; i < 8; i++) acc[i] = 0.f;

    int j = beg;
    for (; j + 3 < end; j += 4) {
        int   s[4];
        float v[4];
        #pragma unroll
        for (int u = 0; u < 4; u++) {
            s[u] = __ldg(&g_esrc[j + u]);
            v[u] = __ldg(&g_eval[j + u]);
        }
        uint4 rw[4];
        #pragma unroll
        for (int u = 0; u < 4; u++) {
            const uint4* r = reinterpret_cast<const uint4*>(h + (size_t)s[u] * D_OUT);
            rw[u] = __ldg(&r[lane]);
        }
        #pragma unroll
        for (int u = 0; u < 4; u++) {
            const __half2* p = reinterpret_cast<const __half2*>(&rw[u]);
            #pragma unroll
            for (int t = 0; t < 4; t++) {
                float2 f = __half22float2(p[t]);
                acc[2 * t]     += f.x * v[u];
                acc[2 * t + 1] += f.y * v[u];
            }
        }
    }
    for (; j < end; j++) {
        const int   s0 = __ldg(&g_esrc[j]);
        const float v0 = __ldg(&g_eval[j]);
        const uint4* r = reinterpret_cast<const uint4*>(h + (size_t)s0 * D_OUT);
        uint4 rw = __ldg(&r[lane]);
        const __half2* p = reinterpret_cast<const __half2*>(&rw);
        #pragma unroll
        for (int t = 0; t < 4; t++) {
            float2 f = __half22float2(p[t]);
            acc[2 * t]     += f.x * v0;
            acc[2 * t + 1] += f.y * v0;
        }
    }

    float4 o0 = make_float4(fmaxf(acc[0], 0.f), fmaxf(acc[1], 0.f),
                            fmaxf(acc[2], 0.f), fmaxf(acc[3], 0.f));
    float4 o1 = make_float4(fmaxf(acc[4], 0.f), fmaxf(acc[5], 0.f),
                            fmaxf(acc[6], 0.f), fmaxf(acc[7], 0.f));

    float4* orow = reinterpret_cast<float4*>(out + (size_t)node * D_OUT);
    orow[2 * lane]     = o0;
    orow[2 * lane + 1] = o1;
}

// ---------------------------------------------------------------------------
// Launch.  CSR build on side stream overlapped with GEMM; gather joins.
// Stream/events created once on the first (non-captured) correctness call.
// ---------------------------------------------------------------------------
extern "C" void kernel_launch(void* const* d_in, const int* in_sizes, int n_in,
                              void* d_out, int out_size)
{
    const float* x    = (const float*)d_in[0];
    const float* W    = (const float*)d_in[1];
    const float* vals = (const float*)d_in[2];
    const void*  src  = d_in[3];
    const void*  dst  = d_in[4];
    float* out = (float*)d_out;

    __half* h;
    cudaGetSymbolAddress((void**)&h, g_h);

    static cudaStream_t side = nullptr;
    static cudaEvent_t  e_fork = nullptr, e_join = nullptr;
    if (side == nullptr) {
        cudaStreamCreateWithFlags(&side, cudaStreamNonBlocking);
        cudaEventCreateWithFlags(&e_fork, cudaEventDisableTiming);
        cudaEventCreateWithFlags(&e_join, cudaEventDisableTiming);
    }

    // fork: side stream joins the capture after this point
    cudaEventRecord(e_fork, 0);
    cudaStreamWaitEvent(side, e_fork, 0);

    // --- side stream: CSR build (independent of GEMM) ---
    zero_detect_kernel<<<(N_NODES + 255) / 256, 256, 0, side>>>((const int*)src);
    count_kernel<<<(N_EDGES + 255) / 256, 256, 0, side>>>(dst);
    scan_kernel<<<1, SCAN_THREADS, 0, side>>>();
    fill_kernel<<<(N_EDGES + 255) / 256, 256, 0, side>>>(src, dst, vals);
    cudaEventRecord(e_join, side);

    // --- main stream: GEMM h = x @ W (fp16 out, overlapped with CSR) ---
    dim3 gemm_grid(D_OUT / 128, (N_NODES + 127) / 128);
    gemm_tf32_kernel<<<gemm_grid, 256>>>(x, W, h);

    // join, then gather-aggregate + ReLU
    cudaStreamWaitEvent(0, e_join, 0);
    gather_kernel<<<(N_NODES + 7) / 8, 256>>>(h, out);
}